// round 3
// baseline (speedup 1.0000x reference)
#include <cuda_runtime.h>
#include <cstdint>

// SPLoPAdapter: out[i*32+a, j*32+b] = weights[.] + sum_k pos[k,i,j]*w[k,a]*h[k,b]
// weights (2048,2048) f32; pos (64,64,64); proto_w (64,32); proto_h (64,32)
//
// CTA: 128 threads, 2x4 group of 32x32 tiles (64x128 outputs). 16 threads/tile,
// each thread an 8x8 patch, f32x2 accumulators. w stored in smem pre-duplicated
// as (w,w) pairs so the hot loop has no per-scalar dup movs.

#define FMA2(acc, av, bv) \
    asm("fma.rn.f32x2 %0, %1, %2, %3;" : "=l"(acc) : "l"(av), "l"(bv), "l"(acc))
#define MUL2(dst, av, bv) \
    asm("mul.rn.f32x2 %0, %1, %2;" : "=l"(dst) : "l"(av), "l"(bv))
#define ADD2(dst, av, bv) \
    asm("add.rn.f32x2 %0, %1, %2;" : "=l"(dst) : "l"(av), "l"(bv))
#define DUP(dst, s) \
    asm("mov.b64 %0, {%1, %1};" : "=l"(dst) : "r"(__float_as_uint(s)))

__global__ void __launch_bounds__(128, 4) splopa_kernel(
    const float* __restrict__ weights,
    const float* __restrict__ pos,
    const float* __restrict__ pw,
    const float* __restrict__ ph,
    float* __restrict__ out)
{
    __shared__ unsigned long long ws[64][32];  // (w,w) dup pairs   16 KB
    __shared__ float hs[2048];                 // h[k][b]            8 KB
    __shared__ float ps_s[64][8];              // pos[k][tile]       2 KB

    const int tid = threadIdx.x;
    const int bi = blockIdx.y;     // 0..31, 64 output rows each
    const int bj = blockIdx.x;     // 0..15, 128 output cols each

    // load h (512 float4, 4 per thread)
    #pragma unroll
    for (int i = 0; i < 4; i++)
        ((float4*)hs)[tid + i * 128] = ((const float4*)ph)[tid + i * 128];

    // load w and store duplicated pairs (2048 values, 16 per thread)
    #pragma unroll
    for (int i = 0; i < 16; i++) {
        const int idx = tid + i * 128;
        const float v = pw[idx];
        unsigned long long d;
        DUP(d, v);
        ((unsigned long long*)ws)[idx] = d;
    }

    // load pos for the 8 tiles (tile t: row t>>2, col t&3)
    #pragma unroll
    for (int i = 0; i < 4; i++) {
        const int idx = tid + i * 128;
        const int t = idx & 7;
        const int k = idx >> 3;
        ps_s[k][t] = pos[k * 4096 + (bi * 2 + (t >> 2)) * 64 + bj * 4 + (t & 3)];
    }
    __syncthreads();

    const int t  = tid >> 4;          // tile 0..7
    const int q  = tid & 15;          // 16 threads per tile
    const int ar = (q >> 2) * 8;      // row base in tile: 0,8,16,24
    const int bc = (q & 3) * 8;       // col base in tile: 0,8,16,24

    unsigned long long acc[8][4];
    #pragma unroll
    for (int a = 0; a < 8; a++)
        #pragma unroll
        for (int j = 0; j < 4; j++)
            acc[a][j] = 0ull;

    #pragma unroll 2
    for (int k = 0; k < 64; k++) {
        unsigned long long ps2;
        DUP(ps2, ps_s[k][t]);

        // h pairs, scaled by pos
        const ulonglong2 h0 = *(const ulonglong2*)&hs[k * 32 + bc];
        const ulonglong2 h1 = *(const ulonglong2*)&hs[k * 32 + bc + 4];
        unsigned long long hp[4];
        MUL2(hp[0], h0.x, ps2);
        MUL2(hp[1], h0.y, ps2);
        MUL2(hp[2], h1.x, ps2);
        MUL2(hp[3], h1.y, ps2);

        // 8 pre-duplicated w pairs
        #pragma unroll
        for (int i = 0; i < 4; i++) {
            const ulonglong2 wv = *(const ulonglong2*)&ws[k][ar + i * 2];
            FMA2(acc[i*2+0][0], wv.x, hp[0]); FMA2(acc[i*2+0][1], wv.x, hp[1]);
            FMA2(acc[i*2+0][2], wv.x, hp[2]); FMA2(acc[i*2+0][3], wv.x, hp[3]);
            FMA2(acc[i*2+1][0], wv.y, hp[0]); FMA2(acc[i*2+1][1], wv.y, hp[1]);
            FMA2(acc[i*2+1][2], wv.y, hp[2]); FMA2(acc[i*2+1][3], wv.y, hp[3]);
        }
    }

    // epilogue: out = weights + acc  (8 rows x 8 cols per thread)
    const int row0 = (bi * 2 + (t >> 2)) * 32 + ar;
    const int col0 = (bj * 4 + (t & 3)) * 32 + bc;

    #pragma unroll
    for (int a = 0; a < 8; a++) {
        const size_t off = (size_t)(row0 + a) * 2048 + col0;
        const ulonglong2 w0 = *(const ulonglong2*)(weights + off);
        const ulonglong2 w1 = *(const ulonglong2*)(weights + off + 4);
        ulonglong2 o0, o1;
        ADD2(o0.x, w0.x, acc[a][0]);
        ADD2(o0.y, w0.y, acc[a][1]);
        ADD2(o1.x, w1.x, acc[a][2]);
        ADD2(o1.y, w1.y, acc[a][3]);
        *(ulonglong2*)(out + off)     = o0;
        *(ulonglong2*)(out + off + 4) = o1;
    }
}

extern "C" void kernel_launch(void* const* d_in, const int* in_sizes, int n_in,
                              void* d_out, int out_size)
{
    const float* weights = (const float*)d_in[0];
    const float* pos     = (const float*)d_in[1];
    const float* pw      = (const float*)d_in[2];
    const float* ph      = (const float*)d_in[3];
    float* out           = (float*)d_out;

    dim3 grid(16, 32);   // 512 CTAs, each 64x128 outputs
    dim3 block(128);
    splopa_kernel<<<grid, block>>>(weights, pos, pw, ph, out);
}

// round 5
// speedup vs baseline: 1.3795x; 1.3795x over previous
#include <cuda_runtime.h>
#include <cuda_bf16.h>
#include <cstdint>

// SPLoPAdapter as ONE GEMM:
//   delta2[ij, ab] = sum_k pos[k, ij] * G[ab, k],  G[ab,k] = w[k,a]*h[k,b]
//   out[i*32+a, j*32+b] = weights[...] + delta2[i*64+j, a*32+b]
// M=4096(ij) x N=1024(ab) x K=64, bf16 mma.sync (m16n8k16), fp32 accum.
// CTA: 256 thr, tile 128x128. Warp: 32(ij) x 64(ab).

static constexpr int AS = 66;   // As row stride (bf16 units), padded
static constexpr int BS = 66;   // Bt row stride (bf16 units), padded

__device__ __forceinline__ void mma_bf16(float* d, const uint32_t* a, const uint32_t* b) {
    asm volatile(
        "mma.sync.aligned.m16n8k16.row.col.f32.bf16.bf16.f32 "
        "{%0,%1,%2,%3}, {%4,%5,%6,%7}, {%8,%9}, {%0,%1,%2,%3};"
        : "+f"(d[0]), "+f"(d[1]), "+f"(d[2]), "+f"(d[3])
        : "r"(a[0]), "r"(a[1]), "r"(a[2]), "r"(a[3]), "r"(b[0]), "r"(b[1]));
}

__global__ void __launch_bounds__(256) splopa_mma_kernel(
    const float* __restrict__ weights,
    const float* __restrict__ pos,
    const float* __restrict__ pw,
    const float* __restrict__ ph,
    float* __restrict__ out)
{
    __shared__ __nv_bfloat16 As[128 * AS];   // A[ijLocal][k] = pos[k, ij]   (~16.5 KB)
    __shared__ __nv_bfloat16 Bt[128 * BS];   // B[abLocal][k] = w[k,a]*h[k,b](~16.5 KB)
    __shared__ float h_s[64 * 32];           // h[k][b]                       (8 KB)
    __shared__ float w_s[64 * 4];            // w[k][a] for this CTA's 4 a's  (1 KB)

    const int tid = threadIdx.x;
    const int wid = tid >> 5;
    const int lane = tid & 31;
    const int g   = lane >> 2;     // groupID 0..7
    const int tig = lane & 3;      // thread-in-group 0..3

    const int ab0 = blockIdx.x * 128;   // ab block (a = ab>>5, b = ab&31)
    const int ij0 = blockIdx.y * 128;   // ij block (i = ij>>6, j = ij&63)

    // ---- stage h (full) and w slice (4 columns a = ab0/32 .. +3) ----
    #pragma unroll
    for (int i = 0; i < 2; i++)
        ((float4*)h_s)[tid + i * 256] = ((const float4*)ph)[tid + i * 256];
    {
        const int k = tid >> 2;
        const int a4 = tid & 3;
        w_s[k * 4 + a4] = pw[k * 32 + (ab0 >> 5) + a4];
    }

    // ---- stage pos slice -> As[ij][k] (bf16, transposed) ----
    #pragma unroll
    for (int it = 0; it < 8; it++) {
        const int chunk = it * 256 + tid;     // 2048 chunks: k row x 32 float4
        const int k = chunk >> 5;
        const int ijc = chunk & 31;
        const float4 p = ((const float4*)(pos + (size_t)k * 4096 + ij0))[ijc];
        const int ijb = ijc * 4;
        As[(ijb + 0) * AS + k] = __float2bfloat16_rn(p.x);
        As[(ijb + 1) * AS + k] = __float2bfloat16_rn(p.y);
        As[(ijb + 2) * AS + k] = __float2bfloat16_rn(p.z);
        As[(ijb + 3) * AS + k] = __float2bfloat16_rn(p.w);
    }
    __syncthreads();   // w_s/h_s ready before G build (and As before main loop)

    // ---- build G slice: Bt[ab][k] = w[k,a]*h[k,b] ----
    {
        const int ab = tid >> 1;       // 0..127
        const int kh = tid & 1;        // low/high 32 k's
        const int asel = ab >> 5;
        const int bsel = ab & 31;
        #pragma unroll
        for (int kk = 0; kk < 32; kk += 2) {
            const int k = kh * 32 + kk;
            const float f0 = w_s[k * 4 + asel]       * h_s[k * 32 + bsel];
            const float f1 = w_s[(k + 1) * 4 + asel] * h_s[(k + 1) * 32 + bsel];
            __nv_bfloat162 pr = __floats2bfloat162_rn(f0, f1);  // low=k, high=k+1
            *(uint32_t*)&Bt[ab * BS + k] = *(uint32_t*)&pr;
        }
    }
    __syncthreads();

    // ---- main GEMM: warp tile 32(ij) x 64(ab) ----
    const int mw = wid >> 1;           // 0..3 -> ij offset
    const int nw = wid & 1;            // 0..1 -> ab offset
    const int ijW = mw * 32;
    const int abW = nw * 64;

    float d[16][4];                    // [mt*8+nt][c]
    #pragma unroll
    for (int x = 0; x < 16; x++)
        #pragma unroll
        for (int c = 0; c < 4; c++)
            d[x][c] = 0.0f;

    #pragma unroll
    for (int kt = 0; kt < 4; kt++) {
        const int kb = kt * 16;

        uint32_t a[2][4];
        #pragma unroll
        for (int mt = 0; mt < 2; mt++) {
            const int r0 = ijW + mt * 16 + g;
            a[mt][0] = *(const uint32_t*)&As[r0 * AS + kb + 2 * tig];
            a[mt][1] = *(const uint32_t*)&As[(r0 + 8) * AS + kb + 2 * tig];
            a[mt][2] = *(const uint32_t*)&As[r0 * AS + kb + 8 + 2 * tig];
            a[mt][3] = *(const uint32_t*)&As[(r0 + 8) * AS + kb + 8 + 2 * tig];
        }

        uint32_t b[8][2];
        #pragma unroll
        for (int nt = 0; nt < 8; nt++) {
            const int col = abW + nt * 8 + g;
            b[nt][0] = *(const uint32_t*)&Bt[col * BS + kb + 2 * tig];
            b[nt][1] = *(const uint32_t*)&Bt[col * BS + kb + 8 + 2 * tig];
        }

        #pragma unroll
        for (int mt = 0; mt < 2; mt++)
            #pragma unroll
            for (int nt = 0; nt < 8; nt++)
                mma_bf16(d[mt * 8 + nt], a[mt], b[nt]);
    }

    // ---- epilogue: scatter + weights add ----
    #pragma unroll
    for (int mt = 0; mt < 2; mt++) {
        const int ijA = ij0 + ijW + mt * 16 + g;
        const int ijB = ijA + 8;
        #pragma unroll
        for (int nt = 0; nt < 8; nt++) {
            const int ab = ab0 + abW + nt * 8 + 2 * tig;
            const int aa = ab >> 5;
            const int bb = ab & 31;
            const float* dd = d[mt * 8 + nt];

            const size_t offA = (size_t)((ijA >> 6) * 32 + aa) * 2048
                              + (size_t)(ijA & 63) * 32 + bb;
            const float2 wvA = *(const float2*)(weights + offA);
            float2 ovA;
            ovA.x = wvA.x + dd[0];
            ovA.y = wvA.y + dd[1];
            *(float2*)(out + offA) = ovA;

            const size_t offB = (size_t)((ijB >> 6) * 32 + aa) * 2048
                              + (size_t)(ijB & 63) * 32 + bb;
            const float2 wvB = *(const float2*)(weights + offB);
            float2 ovB;
            ovB.x = wvB.x + dd[2];
            ovB.y = wvB.y + dd[3];
            *(float2*)(out + offB) = ovB;
        }
    }
}

extern "C" void kernel_launch(void* const* d_in, const int* in_sizes, int n_in,
                              void* d_out, int out_size)
{
    const float* weights = (const float*)d_in[0];
    const float* pos     = (const float*)d_in[1];
    const float* pw      = (const float*)d_in[2];
    const float* ph      = (const float*)d_in[3];
    float* out           = (float*)d_out;

    dim3 grid(8, 32);    // ab-blocks x ij-blocks (256 CTAs)
    dim3 block(256);
    splopa_mma_kernel<<<grid, block>>>(weights, pos, pw, ph, out);
}

// round 6
// speedup vs baseline: 1.5702x; 1.1382x over previous
#include <cuda_runtime.h>
#include <cuda_bf16.h>
#include <cstdint>

// SPLoPAdapter as ONE GEMM:
//   delta2[ij, ab] = sum_k pos[k, ij] * G[ab, k],  G[ab,k] = w[k,a]*h[k,b]
//   out[i*32+a, j*32+b] = weights[...] + delta2[i*64+j, a*32+b]
// M=4096(ij) x N=1024(ab) x K=64, bf16 mma.sync m16n8k16, fp32 accum.
// CTA: 256 thr, tile 128(ij) x 64(ab). Warp: 32x32. Conflict-free padded smem.

static constexpr int ASW = 36;   // As row stride in u32 words (64 bf16 data + pad)
static constexpr int BSW = 36;   // Bt row stride in u32 words
static constexpr int HST = 33;   // h_s row stride in floats

__device__ __forceinline__ void mma_bf16(float* d, const uint32_t* a, const uint32_t* b) {
    asm volatile(
        "mma.sync.aligned.m16n8k16.row.col.f32.bf16.bf16.f32 "
        "{%0,%1,%2,%3}, {%4,%5,%6,%7}, {%8,%9}, {%0,%1,%2,%3};"
        : "+f"(d[0]), "+f"(d[1]), "+f"(d[2]), "+f"(d[3])
        : "r"(a[0]), "r"(a[1]), "r"(a[2]), "r"(a[3]), "r"(b[0]), "r"(b[1]));
}

__device__ __forceinline__ uint32_t packbf(float f0, float f1) {
    __nv_bfloat162 p = __floats2bfloat162_rn(f0, f1);  // low=f0(k), high=f1(k+1)
    return *(uint32_t*)&p;
}

__global__ void __launch_bounds__(256, 3) splopa_mma_kernel(
    const float* __restrict__ weights,
    const float* __restrict__ pos,
    const float* __restrict__ pw,
    const float* __restrict__ ph,
    float* __restrict__ out)
{
    __shared__ uint32_t As32[128 * ASW];   // A[ij][kw] bf16x2 (k,k+1)   18 KB
    __shared__ uint32_t Bt32[64 * BSW];    // B[ab][kw] bf16x2            9 KB
    __shared__ float h_s[64 * HST];        // h[k][b], padded           ~8.4 KB
    __shared__ float w_s[64 * 2];          // w[k][a0..a0+1]             0.5 KB

    const int tid  = threadIdx.x;
    const int wid  = tid >> 5;
    const int lane = tid & 31;
    const int g    = lane >> 2;    // 0..7
    const int tig  = lane & 3;     // 0..3

    const int ab0 = blockIdx.x * 64;    // a = ab>>5 (2 cols), b = ab&31
    const int ij0 = blockIdx.y * 128;   // i = ij>>6, j = ij&63

    // ---- stage h (padded) ----
    #pragma unroll
    for (int it = 0; it < 8; it++) {
        const int idx = tid + it * 256;
        h_s[(idx >> 5) * HST + (idx & 31)] = ph[idx];
    }
    // ---- stage w slice (2 a-columns) ----
    if (tid < 128)
        w_s[tid] = pw[(tid >> 1) * 32 + (ab0 >> 5) + (tid & 1)];

    // ---- stage As[ij][kw]: column-wise reads, STS.128 quads, conflict-free ----
    {
        const int ijl  = tid & 127;
        const int qsel = tid >> 7;                       // 0 or 1
        const float* pb = pos + ij0 + ijl;               // column of pos
        #pragma unroll
        for (int qq = 0; qq < 4; qq++) {
            const int q = qsel * 4 + qq;                 // kw quad: k = 8q..8q+7
            uint32_t pk[4];
            #pragma unroll
            for (int e = 0; e < 4; e++) {
                const float f0 = pb[(size_t)(8 * q + 2 * e) * 4096];
                const float f1 = pb[(size_t)(8 * q + 2 * e + 1) * 4096];
                pk[e] = packbf(f0, f1);
            }
            *(uint4*)&As32[ijl * ASW + 4 * q] = make_uint4(pk[0], pk[1], pk[2], pk[3]);
        }
    }
    __syncthreads();

    // ---- build Bt[ab][kw] = bf16x2( w[k,a]*h[k,b], k & k+1 ) ----
    {
        const int ab   = tid >> 2;          // 0..63
        const int asel = ab >> 5;
        const int bsel = ab & 31;
        #pragma unroll
        for (int qi = 0; qi < 2; qi++) {
            const int q = (tid & 3) * 2 + qi;            // kw quad
            uint32_t pk[4];
            #pragma unroll
            for (int e = 0; e < 4; e++) {
                const int k = 8 * q + 2 * e;
                const float f0 = w_s[k * 2 + asel]       * h_s[k * HST + bsel];
                const float f1 = w_s[(k + 1) * 2 + asel] * h_s[(k + 1) * HST + bsel];
                pk[e] = packbf(f0, f1);
            }
            *(uint4*)&Bt32[ab * BSW + 4 * q] = make_uint4(pk[0], pk[1], pk[2], pk[3]);
        }
    }
    __syncthreads();

    // ---- main GEMM: warp tile 32(ij) x 32(ab) ----
    const int mw = wid >> 1;            // 0..3
    const int nw = wid & 1;             // 0..1
    const int rbase = mw * 32;          // ij base of warp
    const int cbase = nw * 32;          // ab base of warp

    float d[8][4];
    #pragma unroll
    for (int x = 0; x < 8; x++)
        #pragma unroll
        for (int c = 0; c < 4; c++)
            d[x][c] = 0.0f;

    #pragma unroll
    for (int kt = 0; kt < 4; kt++) {
        const int kw0 = kt * 8 + tig;

        uint32_t a[2][4];
        #pragma unroll
        for (int mt = 0; mt < 2; mt++) {
            const int r0 = rbase + mt * 16 + g;
            a[mt][0] = As32[r0 * ASW + kw0];
            a[mt][1] = As32[(r0 + 8) * ASW + kw0];
            a[mt][2] = As32[r0 * ASW + kw0 + 4];
            a[mt][3] = As32[(r0 + 8) * ASW + kw0 + 4];
        }

        uint32_t b[4][2];
        #pragma unroll
        for (int nt = 0; nt < 4; nt++) {
            const int col = cbase + nt * 8 + g;
            b[nt][0] = Bt32[col * BSW + kw0];
            b[nt][1] = Bt32[col * BSW + kw0 + 4];
        }

        #pragma unroll
        for (int mt = 0; mt < 2; mt++)
            #pragma unroll
            for (int nt = 0; nt < 4; nt++)
                mma_bf16(d[mt * 4 + nt], a[mt], b[nt]);
    }

    // ---- epilogue: scatter + weights add ----
    #pragma unroll
    for (int mt = 0; mt < 2; mt++) {
        const int ijA = ij0 + rbase + mt * 16 + g;
        const int ijB = ijA + 8;
        #pragma unroll
        for (int nt = 0; nt < 4; nt++) {
            const int ab = ab0 + cbase + nt * 8 + 2 * tig;
            const int aa = ab >> 5;
            const int bb = ab & 31;
            const float* dd = d[mt * 4 + nt];

            const size_t offA = (size_t)((ijA >> 6) * 32 + aa) * 2048
                              + (size_t)(ijA & 63) * 32 + bb;
            const float2 wvA = *(const float2*)(weights + offA);
            float2 ovA;
            ovA.x = wvA.x + dd[0];
            ovA.y = wvA.y + dd[1];
            *(float2*)(out + offA) = ovA;

            const size_t offB = (size_t)((ijB >> 6) * 32 + aa) * 2048
                              + (size_t)(ijB & 63) * 32 + bb;
            const float2 wvB = *(const float2*)(weights + offB);
            float2 ovB;
            ovB.x = wvB.x + dd[2];
            ovB.y = wvB.y + dd[3];
            *(float2*)(out + offB) = ovB;
        }
    }
}

extern "C" void kernel_launch(void* const* d_in, const int* in_sizes, int n_in,
                              void* d_out, int out_size)
{
    const float* weights = (const float*)d_in[0];
    const float* pos     = (const float*)d_in[1];
    const float* pw      = (const float*)d_in[2];
    const float* ph      = (const float*)d_in[3];
    float* out           = (float*)d_out;

    dim3 grid(16, 32);   // ab-blocks(64) x ij-blocks(128) = 512 CTAs
    dim3 block(256);
    splopa_mma_kernel<<<grid, block>>>(weights, pos, pw, ph, out);
}